// round 11
// baseline (speedup 1.0000x reference)
#include <cuda_runtime.h>
#include <cuda_bf16.h>
#include <cstdint>

#define BATCH 4096
#define DIM   1024
#define NC    1000
#define NTOT  5096
#define NPAD  5120
#define TAU_INV 10.0f
#define EPSF 1e-8f

#define BM 128
#define BN 128
#define BK 32
#define LDA 40              // halves per smem row (32 data + 8 pad)
#define NBLK (NPAD / BN)    // 40
#define NFB  (BATCH / BM)   // 32
#define NTILE 784           // upper-triangle tiles: sum_{bm<32} (40-bm)

// ---- scratch ----
__device__ __nv_bfloat16 g_Gb[NPAD * DIM];
__device__ float g_w[NPAD];
__device__ int   g_cls[NPAD];
__device__ int   g_counts[NC];
__device__ float2 g_dp[NBLK * BATCH];   // (denom, poslog) partials interleaved
__device__ float g_rowv[BATCH];

// ---------------- convert (fp32->bf16, 16 elems/thread) + fused prep in block 0 ----------------
__global__ __launch_bounds__(256) void k_convert(const float* __restrict__ features,
                                                 const float* __restrict__ centers,
                                                 const int* __restrict__ targets) {
    // ---- block 0 additionally performs the prep work (consumed only by later kernels) ----
    if (blockIdx.x == 0) {
        __shared__ int cnt[NC];
        const int tid = threadIdx.x;
        for (int c = tid; c < NC; c += 256) cnt[c] = 0;
        __syncthreads();
        for (int i = tid; i < BATCH; i += 256)
            atomicAdd(&cnt[targets[i]], 1);
        __syncthreads();
        for (int c = tid; c < NC; c += 256) g_counts[c] = cnt[c];
        for (int k = tid; k < NPAD; k += 256) {
            if (k < BATCH) {
                int t = targets[k];
                g_w[k]   = 1.0f / (float)(cnt[t] + 1);
                g_cls[k] = t;
            } else if (k < NTOT) {
                int j = k - BATCH;
                g_w[k]   = 1.0f / (float)(cnt[j] + 1);
                g_cls[k] = j;
            } else {
                g_w[k]   = 0.0f;
                g_cls[k] = -1;
            }
        }
    }

    int idx = blockIdx.x * blockDim.x + threadIdx.x;   // 0 .. NPAD*DIM/16-1
    if (idx >= NPAD * DIM / 16) return;
    int row  = idx >> 6;           // 64 chunks of 16 per row
    int col0 = (idx & 63) << 4;

    float4 v[4];
    if (row < BATCH) {
        const float4* p = reinterpret_cast<const float4*>(features + (size_t)row * DIM + col0);
#pragma unroll
        for (int t = 0; t < 4; t++) v[t] = p[t];
    } else if (row < NTOT) {
        const float4* p = reinterpret_cast<const float4*>(centers + (size_t)(row - BATCH) * DIM + col0);
#pragma unroll
        for (int t = 0; t < 4; t++) v[t] = p[t];
    } else {
#pragma unroll
        for (int t = 0; t < 4; t++) v[t] = make_float4(0.f, 0.f, 0.f, 0.f);
    }
    uint4 pk[2];
    uint32_t* pw = reinterpret_cast<uint32_t*>(pk);
#pragma unroll
    for (int t = 0; t < 4; t++) {
        __nv_bfloat162 lo = __nv_bfloat162(__float2bfloat16_rn(v[t].x), __float2bfloat16_rn(v[t].y));
        __nv_bfloat162 hi = __nv_bfloat162(__float2bfloat16_rn(v[t].z), __float2bfloat16_rn(v[t].w));
        pw[t * 2 + 0] = *reinterpret_cast<uint32_t*>(&lo);
        pw[t * 2 + 1] = *reinterpret_cast<uint32_t*>(&hi);
    }
    uint4* dst = reinterpret_cast<uint4*>(g_Gb + (size_t)row * DIM + col0);
    dst[0] = pk[0];
    dst[1] = pk[1];
}

// ---------------- helpers ----------------
__device__ __forceinline__ void ldmatrix_x4(uint32_t& r0, uint32_t& r1, uint32_t& r2, uint32_t& r3,
                                            uint32_t addr) {
    asm volatile("ldmatrix.sync.aligned.m8n8.x4.shared.b16 {%0,%1,%2,%3}, [%4];"
                 : "=r"(r0), "=r"(r1), "=r"(r2), "=r"(r3) : "r"(addr));
}
__device__ __forceinline__ void ldmatrix_x2(uint32_t& r0, uint32_t& r1, uint32_t addr) {
    asm volatile("ldmatrix.sync.aligned.m8n8.x2.shared.b16 {%0,%1}, [%2];"
                 : "=r"(r0), "=r"(r1) : "r"(addr));
}
__device__ __forceinline__ void mma16816(float* c, uint32_t a0, uint32_t a1, uint32_t a2, uint32_t a3,
                                         uint32_t b0, uint32_t b1) {
    asm volatile(
        "mma.sync.aligned.m16n8k16.row.col.f32.bf16.bf16.f32 "
        "{%0,%1,%2,%3}, {%4,%5,%6,%7}, {%8,%9}, {%0,%1,%2,%3};"
        : "+f"(c[0]), "+f"(c[1]), "+f"(c[2]), "+f"(c[3])
        : "r"(a0), "r"(a1), "r"(a2), "r"(a3), "r"(b0), "r"(b1));
}
__device__ __forceinline__ void cp16(uint32_t dst, const void* src) {
    asm volatile("cp.async.cg.shared.global [%0], [%1], 16;" :: "r"(dst), "l"(src));
}
#define CP_COMMIT() asm volatile("cp.async.commit_group;")
#define CP_WAIT(n)  asm volatile("cp.async.wait_group %0;" :: "n"(n))

// ---------------- fused GEMM + dual-role epilogue ----------------
__global__ __launch_bounds__(256, 2) void k_gemm() {
    int t = blockIdx.x;
    int bm = 0;
    while (t >= NBLK - bm) { t -= NBLK - bm; bm++; }
    const int bn = bm + t;

    __shared__ __align__(16) __nv_bfloat16 sA[2][BM * LDA];
    __shared__ __align__(16) __nv_bfloat16 sB[2][BN * LDA];
    __shared__ float red_d[BM];
    __shared__ float red_p[BM];
    __shared__ float cred_d[BN];
    __shared__ float cred_p[BN];
    __shared__ float sWr[BM];

    const int tid  = threadIdx.x;
    const int warp = tid >> 5;
    const int lane = tid & 31;
    const int wm = warp >> 2;
    const int wn = warp & 3;
    const int rowBase = bm * BM;
    const int colBase = bn * BN;
    const bool doTrans = (bn > bm) && (bn < NFB);

    if (tid < BM) {
        red_d[tid] = 0.0f; red_p[tid] = 0.0f;
        cred_d[tid] = 0.0f; cred_p[tid] = 0.0f;
        sWr[tid] = g_w[rowBase + tid];
    }

    float acc[4][4][4];
#pragma unroll
    for (int a = 0; a < 4; a++)
#pragma unroll
        for (int b = 0; b < 4; b++)
#pragma unroll
            for (int c = 0; c < 4; c++) acc[a][b][c] = 0.0f;

    const int r0 = tid >> 2;
    const int r1 = r0 + 64;
    const int q  = tid & 3;
    const uint4* gA0 = reinterpret_cast<const uint4*>(g_Gb) + (size_t)(rowBase + r0) * (DIM / 8) + q;
    const uint4* gA1 = reinterpret_cast<const uint4*>(g_Gb) + (size_t)(rowBase + r1) * (DIM / 8) + q;
    const uint4* gB0 = reinterpret_cast<const uint4*>(g_Gb) + (size_t)(colBase + r0) * (DIM / 8) + q;
    const uint4* gB1 = reinterpret_cast<const uint4*>(g_Gb) + (size_t)(colBase + r1) * (DIM / 8) + q;

    uint32_t dA0[2], dA1[2], dB0[2], dB1[2];
#pragma unroll
    for (int s = 0; s < 2; s++) {
        dA0[s] = (uint32_t)__cvta_generic_to_shared(&sA[s][r0 * LDA + q * 8]);
        dA1[s] = (uint32_t)__cvta_generic_to_shared(&sA[s][r1 * LDA + q * 8]);
        dB0[s] = (uint32_t)__cvta_generic_to_shared(&sB[s][r0 * LDA + q * 8]);
        dB1[s] = (uint32_t)__cvta_generic_to_shared(&sB[s][r1 * LDA + q * 8]);
    }

    cp16(dA0[0], gA0); cp16(dA1[0], gA1);
    cp16(dB0[0], gB0); cp16(dB1[0], gB1);
    CP_COMMIT();

    const int KT = DIM / BK;
    const int aRow = wm * 64 + (lane & 15);
    const int aCol = (lane >> 4) << 3;
    const int bRow = wn * 32 + (lane & 7);
    const int bCol = ((lane >> 3) & 1) << 3;

    for (int kt = 0; kt < KT; kt++) {
        const int cur = kt & 1;
        if (kt + 1 < KT) {
            const int nxt = cur ^ 1;
            const int kq = (kt + 1) * 4;
            cp16(dA0[nxt], gA0 + kq); cp16(dA1[nxt], gA1 + kq);
            cp16(dB0[nxt], gB0 + kq); cp16(dB1[nxt], gB1 + kq);
            CP_COMMIT();
            CP_WAIT(1);
        } else {
            CP_WAIT(0);
        }
        __syncthreads();

        const uint32_t baseA = (uint32_t)__cvta_generic_to_shared(&sA[cur][0]);
        const uint32_t baseB = (uint32_t)__cvta_generic_to_shared(&sB[cur][0]);

#pragma unroll
        for (int kk = 0; kk < 2; kk++) {
            uint32_t af[4][4];
#pragma unroll
            for (int mt = 0; mt < 4; mt++) {
                uint32_t addr = baseA + (uint32_t)(((aRow + mt * 16) * LDA + kk * 16 + aCol) << 1);
                ldmatrix_x4(af[mt][0], af[mt][1], af[mt][2], af[mt][3], addr);
            }
            uint32_t bf[4][2];
#pragma unroll
            for (int nt = 0; nt < 4; nt++) {
                uint32_t addr = baseB + (uint32_t)(((bRow + nt * 8) * LDA + kk * 16 + bCol) << 1);
                ldmatrix_x2(bf[nt][0], bf[nt][1], addr);
            }
#pragma unroll
            for (int mt = 0; mt < 4; mt++)
#pragma unroll
                for (int nt = 0; nt < 4; nt++)
                    mma16816(acc[mt][nt], af[mt][0], af[mt][1], af[mt][2], af[mt][3],
                             bf[nt][0], bf[nt][1]);
        }
        if (kt + 1 < KT) __syncthreads();
    }

    // ---------- epilogue ----------
    // log(exp(s)+eps) == s + log1p(eps*exp(-s)) ~= s  (correction <= 2.2e-4 worst case)
    const int g = lane >> 2;
    const int tl = lane & 3;

    float wv[4][2];
    int   cl[4][2];
    int   kc[4][2];
#pragma unroll
    for (int nt = 0; nt < 4; nt++)
#pragma unroll
        for (int j = 0; j < 2; j++) {
            int k = colBase + wn * 32 + nt * 8 + tl * 2 + j;
            kc[nt][j] = k;
            wv[nt][j] = g_w[k];
            cl[nt][j] = g_cls[k];
        }

    float cds[4][2], cps[4][2];
#pragma unroll
    for (int nt = 0; nt < 4; nt++)
#pragma unroll
        for (int j = 0; j < 2; j++) { cds[nt][j] = 0.0f; cps[nt][j] = 0.0f; }

#pragma unroll
    for (int mt = 0; mt < 4; mt++) {
#pragma unroll
        for (int h = 0; h < 2; h++) {
            const int lr = wm * 64 + mt * 16 + g + h * 8;
            const int i  = rowBase + lr;
            const int ti = g_cls[i];
            const float wr = sWr[lr];
            float ds = 0.0f, ps = 0.0f;
#pragma unroll
            for (int nt = 0; nt < 4; nt++)
#pragma unroll
                for (int j = 0; j < 2; j++) {
                    const float s = acc[mt][nt][h * 2 + j] * TAU_INV;
                    const float e = __expf(s);
                    ds += e * wv[nt][j];
                    float lg = 0.0f;
                    if (cl[nt][j] == ti && kc[nt][j] != i) lg = s;
                    ps += lg;
                    if (doTrans) {
                        cds[nt][j] += e * wr;
                        cps[nt][j] += lg;
                    }
                }
            ds += __shfl_xor_sync(0xffffffffu, ds, 1);
            ds += __shfl_xor_sync(0xffffffffu, ds, 2);
            ps += __shfl_xor_sync(0xffffffffu, ps, 1);
            ps += __shfl_xor_sync(0xffffffffu, ps, 2);
            if (tl == 0) {
                atomicAdd(&red_d[lr], ds);
                atomicAdd(&red_p[lr], ps);
            }
        }
    }

    if (doTrans) {
#pragma unroll
        for (int nt = 0; nt < 4; nt++)
#pragma unroll
            for (int j = 0; j < 2; j++) {
                float v = cds[nt][j], p = cps[nt][j];
                v += __shfl_xor_sync(0xffffffffu, v, 4);
                v += __shfl_xor_sync(0xffffffffu, v, 8);
                v += __shfl_xor_sync(0xffffffffu, v, 16);
                p += __shfl_xor_sync(0xffffffffu, p, 4);
                p += __shfl_xor_sync(0xffffffffu, p, 8);
                p += __shfl_xor_sync(0xffffffffu, p, 16);
                if (g == 0) {
                    const int ck = wn * 32 + nt * 8 + tl * 2 + j;
                    atomicAdd(&cred_d[ck], v);
                    atomicAdd(&cred_p[ck], p);
                }
            }
    }
    __syncthreads();

    if (tid < BM) {
        g_dp[bn * BATCH + rowBase + tid] = make_float2(red_d[tid], red_p[tid]);
        if (doTrans)
            g_dp[bm * BATCH + colBase + tid] = make_float2(cred_d[tid], cred_p[tid]);
    }
}

// ---------------- finalize stage 1: per-row, 128 blocks, 4-way MLP ----------------
__global__ void k_final1(const int* __restrict__ targets) {
    const int r = blockIdx.x * 32 + threadIdx.x;   // 128 blocks x 32 threads
    float d0 = 0.f, d1 = 0.f, d2 = 0.f, d3 = 0.f;
    float p0 = 0.f, p1 = 0.f, p2 = 0.f, p3 = 0.f;
#pragma unroll
    for (int b = 0; b < NBLK; b += 4) {
        float2 v0 = g_dp[(b + 0) * BATCH + r];
        float2 v1 = g_dp[(b + 1) * BATCH + r];
        float2 v2 = g_dp[(b + 2) * BATCH + r];
        float2 v3 = g_dp[(b + 3) * BATCH + r];
        d0 += v0.x; p0 += v0.y;
        d1 += v1.x; p1 += v1.y;
        d2 += v2.x; p2 += v2.y;
        d3 += v3.x; p3 += v3.y;
    }
    const float d = (d0 + d1) + (d2 + d3);
    const float p = (p0 + p1) + (p2 + p3);
    const float np = (float)g_counts[targets[r]];
    g_rowv[r] = logf(d + EPSF) - p / np;
}

// ---------------- finalize stage 2: deterministic tree reduce ----------------
__global__ void k_final2(float* __restrict__ out) {
    __shared__ float sred[1024];
    const int tid = threadIdx.x;
    float local = 0.0f;
    for (int r = tid; r < BATCH; r += 1024) local += g_rowv[r];
    sred[tid] = local;
    __syncthreads();
    for (int s = 512; s > 0; s >>= 1) {
        if (tid < s) sred[tid] += sred[tid + s];
        __syncthreads();
    }
    if (tid == 0) out[0] = sred[0] / (float)BATCH;
}

// ---------------- launch ----------------
extern "C" void kernel_launch(void* const* d_in, const int* in_sizes, int n_in,
                              void* d_out, int out_size) {
    const float* centers  = nullptr;
    const float* features = nullptr;
    const int*   targets  = nullptr;
    for (int i = 0; i < n_in; i++) {
        if (in_sizes[i] == BATCH)            targets  = (const int*)d_in[i];
        else if (in_sizes[i] == BATCH * DIM) features = (const float*)d_in[i];
        else if (in_sizes[i] == NC * DIM)    centers  = (const float*)d_in[i];
    }

    k_convert<<<(NPAD * DIM / 16 + 255) / 256, 256>>>(features, centers, targets);

    k_gemm<<<NTILE, 256>>>();

    k_final1<<<BATCH / 32, 32>>>(targets);
    k_final2<<<1, 1024>>>((float*)d_out);
}

// round 12
// speedup vs baseline: 1.0382x; 1.0382x over previous
#include <cuda_runtime.h>
#include <cuda_bf16.h>
#include <cstdint>

#define BATCH 4096
#define DIM   1024
#define NC    1000
#define NTOT  5096
#define NPAD  5120
#define TAU_INV 10.0f
#define EPSF 1e-8f

#define BM 128
#define BN 128
#define BK 32
#define LDA 40              // halves per smem row (32 data + 8 pad)
#define NBLK (NPAD / BN)    // 40
#define NFB  (BATCH / BM)   // 32
#define NTILE 784           // upper-triangle tiles: sum_{bm<32} (40-bm)

// ---- scratch ----
__device__ __nv_bfloat16 g_Gb[NPAD * DIM];
__device__ float g_w[NPAD];
__device__ int   g_cls[NPAD];
__device__ int   g_counts[NC];
__device__ float2 g_dp[NBLK * BATCH];   // (denom, poslog) partials interleaved
__device__ float g_rowv[BATCH];
__device__ int   g_done = 0;            // ticket counter; last block resets to 0

// ---------------- fused prep: counts + weights + classes (1 block) ----------------
__global__ __launch_bounds__(1024) void k_prep(const int* __restrict__ targets) {
    __shared__ int cnt[NC];
    const int tid = threadIdx.x;
    if (tid < NC) cnt[tid] = 0;
    __syncthreads();
#pragma unroll
    for (int i = tid; i < BATCH; i += 1024)
        atomicAdd(&cnt[targets[i]], 1);
    __syncthreads();
    if (tid < NC) g_counts[tid] = cnt[tid];
#pragma unroll
    for (int k = tid; k < NPAD; k += 1024) {
        if (k < BATCH) {
            int t = targets[k];
            g_w[k]   = 1.0f / (float)(cnt[t] + 1);
            g_cls[k] = t;
        } else if (k < NTOT) {
            int j = k - BATCH;
            g_w[k]   = 1.0f / (float)(cnt[j] + 1);
            g_cls[k] = j;
        } else {
            g_w[k]   = 0.0f;
            g_cls[k] = -1;
        }
    }
}

// ---------------- convert: fp32 -> bf16, 16 elems (32B out) per thread ----------------
__global__ __launch_bounds__(256) void k_convert(const float* __restrict__ features,
                                                 const float* __restrict__ centers) {
    int idx = blockIdx.x * blockDim.x + threadIdx.x;   // 0 .. NPAD*DIM/16-1
    if (idx >= NPAD * DIM / 16) return;
    int row  = idx >> 6;           // 64 chunks of 16 per row
    int col0 = (idx & 63) << 4;

    float4 v[4];
    if (row < BATCH) {
        const float4* p = reinterpret_cast<const float4*>(features + (size_t)row * DIM + col0);
#pragma unroll
        for (int t = 0; t < 4; t++) v[t] = p[t];
    } else if (row < NTOT) {
        const float4* p = reinterpret_cast<const float4*>(centers + (size_t)(row - BATCH) * DIM + col0);
#pragma unroll
        for (int t = 0; t < 4; t++) v[t] = p[t];
    } else {
#pragma unroll
        for (int t = 0; t < 4; t++) v[t] = make_float4(0.f, 0.f, 0.f, 0.f);
    }
    uint4 pk[2];
    uint32_t* pw = reinterpret_cast<uint32_t*>(pk);
#pragma unroll
    for (int t = 0; t < 4; t++) {
        __nv_bfloat162 lo = __nv_bfloat162(__float2bfloat16_rn(v[t].x), __float2bfloat16_rn(v[t].y));
        __nv_bfloat162 hi = __nv_bfloat162(__float2bfloat16_rn(v[t].z), __float2bfloat16_rn(v[t].w));
        pw[t * 2 + 0] = *reinterpret_cast<uint32_t*>(&lo);
        pw[t * 2 + 1] = *reinterpret_cast<uint32_t*>(&hi);
    }
    uint4* dst = reinterpret_cast<uint4*>(g_Gb + (size_t)row * DIM + col0);
    dst[0] = pk[0];
    dst[1] = pk[1];
}

// ---------------- helpers ----------------
__device__ __forceinline__ void ldmatrix_x4(uint32_t& r0, uint32_t& r1, uint32_t& r2, uint32_t& r3,
                                            uint32_t addr) {
    asm volatile("ldmatrix.sync.aligned.m8n8.x4.shared.b16 {%0,%1,%2,%3}, [%4];"
                 : "=r"(r0), "=r"(r1), "=r"(r2), "=r"(r3) : "r"(addr));
}
__device__ __forceinline__ void ldmatrix_x2(uint32_t& r0, uint32_t& r1, uint32_t addr) {
    asm volatile("ldmatrix.sync.aligned.m8n8.x2.shared.b16 {%0,%1}, [%2];"
                 : "=r"(r0), "=r"(r1) : "r"(addr));
}
__device__ __forceinline__ void mma16816(float* c, uint32_t a0, uint32_t a1, uint32_t a2, uint32_t a3,
                                         uint32_t b0, uint32_t b1) {
    asm volatile(
        "mma.sync.aligned.m16n8k16.row.col.f32.bf16.bf16.f32 "
        "{%0,%1,%2,%3}, {%4,%5,%6,%7}, {%8,%9}, {%0,%1,%2,%3};"
        : "+f"(c[0]), "+f"(c[1]), "+f"(c[2]), "+f"(c[3])
        : "r"(a0), "r"(a1), "r"(a2), "r"(a3), "r"(b0), "r"(b1));
}
__device__ __forceinline__ void cp16(uint32_t dst, const void* src) {
    asm volatile("cp.async.cg.shared.global [%0], [%1], 16;" :: "r"(dst), "l"(src));
}
#define CP_COMMIT() asm volatile("cp.async.commit_group;")
#define CP_WAIT(n)  asm volatile("cp.async.wait_group %0;" :: "n"(n))

// ---------------- fused GEMM + dual-role epilogue (unchanged mainloop) ----------------
__global__ __launch_bounds__(256, 2) void k_gemm() {
    int t = blockIdx.x;
    int bm = 0;
    while (t >= NBLK - bm) { t -= NBLK - bm; bm++; }
    const int bn = bm + t;

    __shared__ __align__(16) __nv_bfloat16 sA[2][BM * LDA];
    __shared__ __align__(16) __nv_bfloat16 sB[2][BN * LDA];
    __shared__ float red_d[BM];
    __shared__ float red_p[BM];
    __shared__ float cred_d[BN];
    __shared__ float cred_p[BN];
    __shared__ float sWr[BM];

    const int tid  = threadIdx.x;
    const int warp = tid >> 5;
    const int lane = tid & 31;
    const int wm = warp >> 2;
    const int wn = warp & 3;
    const int rowBase = bm * BM;
    const int colBase = bn * BN;
    const bool doTrans = (bn > bm) && (bn < NFB);

    if (tid < BM) {
        red_d[tid] = 0.0f; red_p[tid] = 0.0f;
        cred_d[tid] = 0.0f; cred_p[tid] = 0.0f;
        sWr[tid] = g_w[rowBase + tid];
    }

    float acc[4][4][4];
#pragma unroll
    for (int a = 0; a < 4; a++)
#pragma unroll
        for (int b = 0; b < 4; b++)
#pragma unroll
            for (int c = 0; c < 4; c++) acc[a][b][c] = 0.0f;

    const int r0 = tid >> 2;
    const int r1 = r0 + 64;
    const int q  = tid & 3;
    const uint4* gA0 = reinterpret_cast<const uint4*>(g_Gb) + (size_t)(rowBase + r0) * (DIM / 8) + q;
    const uint4* gA1 = reinterpret_cast<const uint4*>(g_Gb) + (size_t)(rowBase + r1) * (DIM / 8) + q;
    const uint4* gB0 = reinterpret_cast<const uint4*>(g_Gb) + (size_t)(colBase + r0) * (DIM / 8) + q;
    const uint4* gB1 = reinterpret_cast<const uint4*>(g_Gb) + (size_t)(colBase + r1) * (DIM / 8) + q;

    uint32_t dA0[2], dA1[2], dB0[2], dB1[2];
#pragma unroll
    for (int s = 0; s < 2; s++) {
        dA0[s] = (uint32_t)__cvta_generic_to_shared(&sA[s][r0 * LDA + q * 8]);
        dA1[s] = (uint32_t)__cvta_generic_to_shared(&sA[s][r1 * LDA + q * 8]);
        dB0[s] = (uint32_t)__cvta_generic_to_shared(&sB[s][r0 * LDA + q * 8]);
        dB1[s] = (uint32_t)__cvta_generic_to_shared(&sB[s][r1 * LDA + q * 8]);
    }

    cp16(dA0[0], gA0); cp16(dA1[0], gA1);
    cp16(dB0[0], gB0); cp16(dB1[0], gB1);
    CP_COMMIT();

    const int KT = DIM / BK;
    const int aRow = wm * 64 + (lane & 15);
    const int aCol = (lane >> 4) << 3;
    const int bRow = wn * 32 + (lane & 7);
    const int bCol = ((lane >> 3) & 1) << 3;

    for (int kt = 0; kt < KT; kt++) {
        const int cur = kt & 1;
        if (kt + 1 < KT) {
            const int nxt = cur ^ 1;
            const int kq = (kt + 1) * 4;
            cp16(dA0[nxt], gA0 + kq); cp16(dA1[nxt], gA1 + kq);
            cp16(dB0[nxt], gB0 + kq); cp16(dB1[nxt], gB1 + kq);
            CP_COMMIT();
            CP_WAIT(1);
        } else {
            CP_WAIT(0);
        }
        __syncthreads();

        const uint32_t baseA = (uint32_t)__cvta_generic_to_shared(&sA[cur][0]);
        const uint32_t baseB = (uint32_t)__cvta_generic_to_shared(&sB[cur][0]);

#pragma unroll
        for (int kk = 0; kk < 2; kk++) {
            uint32_t af[4][4];
#pragma unroll
            for (int mt = 0; mt < 4; mt++) {
                uint32_t addr = baseA + (uint32_t)(((aRow + mt * 16) * LDA + kk * 16 + aCol) << 1);
                ldmatrix_x4(af[mt][0], af[mt][1], af[mt][2], af[mt][3], addr);
            }
            uint32_t bf[4][2];
#pragma unroll
            for (int nt = 0; nt < 4; nt++) {
                uint32_t addr = baseB + (uint32_t)(((bRow + nt * 8) * LDA + kk * 16 + bCol) << 1);
                ldmatrix_x2(bf[nt][0], bf[nt][1], addr);
            }
#pragma unroll
            for (int mt = 0; mt < 4; mt++)
#pragma unroll
                for (int nt = 0; nt < 4; nt++)
                    mma16816(acc[mt][nt], af[mt][0], af[mt][1], af[mt][2], af[mt][3],
                             bf[nt][0], bf[nt][1]);
        }
        if (kt + 1 < KT) __syncthreads();
    }

    // ---------- epilogue ----------
    const int g = lane >> 2;
    const int tl = lane & 3;

    float wv[4][2];
    int   cl[4][2];
    int   kc[4][2];
#pragma unroll
    for (int nt = 0; nt < 4; nt++)
#pragma unroll
        for (int j = 0; j < 2; j++) {
            int k = colBase + wn * 32 + nt * 8 + tl * 2 + j;
            kc[nt][j] = k;
            wv[nt][j] = g_w[k];
            cl[nt][j] = g_cls[k];
        }

    float cds[4][2], cps[4][2];
#pragma unroll
    for (int nt = 0; nt < 4; nt++)
#pragma unroll
        for (int j = 0; j < 2; j++) { cds[nt][j] = 0.0f; cps[nt][j] = 0.0f; }

#pragma unroll
    for (int mt = 0; mt < 4; mt++) {
#pragma unroll
        for (int h = 0; h < 2; h++) {
            const int lr = wm * 64 + mt * 16 + g + h * 8;
            const int i  = rowBase + lr;
            const int ti = g_cls[i];
            const float wr = sWr[lr];
            float ds = 0.0f, ps = 0.0f;
#pragma unroll
            for (int nt = 0; nt < 4; nt++)
#pragma unroll
                for (int j = 0; j < 2; j++) {
                    const float s = acc[mt][nt][h * 2 + j] * TAU_INV;
                    const float e = __expf(s);
                    ds += e * wv[nt][j];
                    float lg = 0.0f;
                    if (cl[nt][j] == ti && kc[nt][j] != i) lg = s;
                    ps += lg;
                    if (doTrans) {
                        cds[nt][j] += e * wr;
                        cps[nt][j] += lg;
                    }
                }
            ds += __shfl_xor_sync(0xffffffffu, ds, 1);
            ds += __shfl_xor_sync(0xffffffffu, ds, 2);
            ps += __shfl_xor_sync(0xffffffffu, ps, 1);
            ps += __shfl_xor_sync(0xffffffffu, ps, 2);
            if (tl == 0) {
                atomicAdd(&red_d[lr], ds);
                atomicAdd(&red_p[lr], ps);
            }
        }
    }

    if (doTrans) {
#pragma unroll
        for (int nt = 0; nt < 4; nt++)
#pragma unroll
            for (int j = 0; j < 2; j++) {
                float v = cds[nt][j], p = cps[nt][j];
                v += __shfl_xor_sync(0xffffffffu, v, 4);
                v += __shfl_xor_sync(0xffffffffu, v, 8);
                v += __shfl_xor_sync(0xffffffffu, v, 16);
                p += __shfl_xor_sync(0xffffffffu, p, 4);
                p += __shfl_xor_sync(0xffffffffu, p, 8);
                p += __shfl_xor_sync(0xffffffffu, p, 16);
                if (g == 0) {
                    const int ck = wn * 32 + nt * 8 + tl * 2 + j;
                    atomicAdd(&cred_d[ck], v);
                    atomicAdd(&cred_p[ck], p);
                }
            }
    }
    __syncthreads();

    if (tid < BM) {
        g_dp[bn * BATCH + rowBase + tid] = make_float2(red_d[tid], red_p[tid]);
        if (doTrans)
            g_dp[bm * BATCH + colBase + tid] = make_float2(cred_d[tid], cred_p[tid]);
    }
}

// ---------------- finalize: per-row + last-block global reduce (one launch) ----------------
__global__ void k_final(const int* __restrict__ targets, float* __restrict__ out) {
    const int r = blockIdx.x * 32 + threadIdx.x;   // 128 blocks x 32 threads
    float d0 = 0.f, d1 = 0.f, d2 = 0.f, d3 = 0.f;
    float p0 = 0.f, p1 = 0.f, p2 = 0.f, p3 = 0.f;
#pragma unroll
    for (int b = 0; b < NBLK; b += 4) {
        float2 v0 = g_dp[(b + 0) * BATCH + r];
        float2 v1 = g_dp[(b + 1) * BATCH + r];
        float2 v2 = g_dp[(b + 2) * BATCH + r];
        float2 v3 = g_dp[(b + 3) * BATCH + r];
        d0 += v0.x; p0 += v0.y;
        d1 += v1.x; p1 += v1.y;
        d2 += v2.x; p2 += v2.y;
        d3 += v3.x; p3 += v3.y;
    }
    const float d = (d0 + d1) + (d2 + d3);
    const float p = (p0 + p1) + (p2 + p3);
    const float np = (float)g_counts[targets[r]];
    g_rowv[r] = logf(d + EPSF) - p / np;

    // last-block-done global reduction (deterministic: fixed index order)
    __threadfence();
    __shared__ int isLast;
    if (threadIdx.x == 0)
        isLast = (atomicAdd(&g_done, 1) == gridDim.x - 1) ? 1 : 0;
    __syncthreads();
    if (isLast) {
        float a0 = 0.f, a1 = 0.f, a2 = 0.f, a3 = 0.f;
        const int lane = threadIdx.x;
#pragma unroll
        for (int i = 0; i < BATCH; i += 128) {
            a0 += g_rowv[i + lane];
            a1 += g_rowv[i + 32 + lane];
            a2 += g_rowv[i + 64 + lane];
            a3 += g_rowv[i + 96 + lane];
        }
        float local = (a0 + a1) + (a2 + a3);
#pragma unroll
        for (int m = 16; m > 0; m >>= 1)
            local += __shfl_xor_sync(0xffffffffu, local, m);
        if (lane == 0) {
            out[0] = local / (float)BATCH;
            g_done = 0;    // reset for next graph replay
        }
    }
}

// ---------------- launch ----------------
extern "C" void kernel_launch(void* const* d_in, const int* in_sizes, int n_in,
                              void* d_out, int out_size) {
    const float* centers  = nullptr;
    const float* features = nullptr;
    const int*   targets  = nullptr;
    for (int i = 0; i < n_in; i++) {
        if (in_sizes[i] == BATCH)            targets  = (const int*)d_in[i];
        else if (in_sizes[i] == BATCH * DIM) features = (const float*)d_in[i];
        else if (in_sizes[i] == NC * DIM)    centers  = (const float*)d_in[i];
    }

    k_prep<<<1, 1024>>>(targets);
    k_convert<<<(NPAD * DIM / 16 + 255) / 256, 256>>>(features, centers);

    k_gemm<<<NTILE, 256>>>();

    k_final<<<BATCH / 32, 32>>>(targets, (float*)d_out);
}

// round 13
// speedup vs baseline: 1.0462x; 1.0077x over previous
#include <cuda_runtime.h>
#include <cuda_bf16.h>
#include <cstdint>

#define BATCH 4096
#define DIM   1024
#define NC    1000
#define NTOT  5096
#define NPAD  5120
#define TAU_INV 10.0f
#define EPSF 1e-8f

#define BM 128
#define BN 128
#define BK 32
#define LDA 40              // halves per smem row (32 data + 8 pad)
#define NBLK (NPAD / BN)    // 40
#define NFB  (BATCH / BM)   // 32
#define NTILE 784           // upper-triangle tiles: sum_{bm<32} (40-bm)

// ---- scratch ----
__device__ __nv_bfloat16 g_Gb[NPAD * DIM];
__device__ float g_w[NPAD];
__device__ int   g_cls[NPAD];
__device__ int   g_counts[NC];
__device__ float2 g_dp[NBLK * BATCH];   // (denom, poslog) partials interleaved
__device__ float g_rowv[BATCH];
__device__ int   g_done = 0;            // ticket counter; last block resets to 0

// ---------------- fused prep: counts + weights + classes (1 block) ----------------
__global__ __launch_bounds__(1024) void k_prep(const int* __restrict__ targets) {
    __shared__ int cnt[NC];
    const int tid = threadIdx.x;
    if (tid < NC) cnt[tid] = 0;
    __syncthreads();
#pragma unroll
    for (int i = tid; i < BATCH; i += 1024)
        atomicAdd(&cnt[targets[i]], 1);
    __syncthreads();
    if (tid < NC) g_counts[tid] = cnt[tid];
#pragma unroll
    for (int k = tid; k < NPAD; k += 1024) {
        if (k < BATCH) {
            int t = targets[k];
            g_w[k]   = 1.0f / (float)(cnt[t] + 1);
            g_cls[k] = t;
        } else if (k < NTOT) {
            int j = k - BATCH;
            g_w[k]   = 1.0f / (float)(cnt[j] + 1);
            g_cls[k] = j;
        } else {
            g_w[k]   = 0.0f;
            g_cls[k] = -1;
        }
    }
}

// ---------------- convert: fp32 -> bf16, 16 elems (32B out) per thread ----------------
__global__ __launch_bounds__(256) void k_convert(const float* __restrict__ features,
                                                 const float* __restrict__ centers) {
    int idx = blockIdx.x * blockDim.x + threadIdx.x;   // 0 .. NPAD*DIM/16-1
    if (idx >= NPAD * DIM / 16) return;
    int row  = idx >> 6;           // 64 chunks of 16 per row
    int col0 = (idx & 63) << 4;

    float4 v[4];
    if (row < BATCH) {
        const float4* p = reinterpret_cast<const float4*>(features + (size_t)row * DIM + col0);
#pragma unroll
        for (int t = 0; t < 4; t++) v[t] = p[t];
    } else if (row < NTOT) {
        const float4* p = reinterpret_cast<const float4*>(centers + (size_t)(row - BATCH) * DIM + col0);
#pragma unroll
        for (int t = 0; t < 4; t++) v[t] = p[t];
    } else {
#pragma unroll
        for (int t = 0; t < 4; t++) v[t] = make_float4(0.f, 0.f, 0.f, 0.f);
    }
    uint4 pk[2];
    uint32_t* pw = reinterpret_cast<uint32_t*>(pk);
#pragma unroll
    for (int t = 0; t < 4; t++) {
        __nv_bfloat162 lo = __nv_bfloat162(__float2bfloat16_rn(v[t].x), __float2bfloat16_rn(v[t].y));
        __nv_bfloat162 hi = __nv_bfloat162(__float2bfloat16_rn(v[t].z), __float2bfloat16_rn(v[t].w));
        pw[t * 2 + 0] = *reinterpret_cast<uint32_t*>(&lo);
        pw[t * 2 + 1] = *reinterpret_cast<uint32_t*>(&hi);
    }
    uint4* dst = reinterpret_cast<uint4*>(g_Gb + (size_t)row * DIM + col0);
    dst[0] = pk[0];
    dst[1] = pk[1];
}

// ---------------- helpers ----------------
__device__ __forceinline__ void ldmatrix_x4(uint32_t& r0, uint32_t& r1, uint32_t& r2, uint32_t& r3,
                                            uint32_t addr) {
    asm volatile("ldmatrix.sync.aligned.m8n8.x4.shared.b16 {%0,%1,%2,%3}, [%4];"
                 : "=r"(r0), "=r"(r1), "=r"(r2), "=r"(r3) : "r"(addr));
}
__device__ __forceinline__ void ldmatrix_x2(uint32_t& r0, uint32_t& r1, uint32_t addr) {
    asm volatile("ldmatrix.sync.aligned.m8n8.x2.shared.b16 {%0,%1}, [%2];"
                 : "=r"(r0), "=r"(r1) : "r"(addr));
}
__device__ __forceinline__ void mma16816(float* c, uint32_t a0, uint32_t a1, uint32_t a2, uint32_t a3,
                                         uint32_t b0, uint32_t b1) {
    asm volatile(
        "mma.sync.aligned.m16n8k16.row.col.f32.bf16.bf16.f32 "
        "{%0,%1,%2,%3}, {%4,%5,%6,%7}, {%8,%9}, {%0,%1,%2,%3};"
        : "+f"(c[0]), "+f"(c[1]), "+f"(c[2]), "+f"(c[3])
        : "r"(a0), "r"(a1), "r"(a2), "r"(a3), "r"(b0), "r"(b1));
}
__device__ __forceinline__ void cp16(uint32_t dst, const void* src) {
    asm volatile("cp.async.cg.shared.global [%0], [%1], 16;" :: "r"(dst), "l"(src));
}
#define CP_COMMIT() asm volatile("cp.async.commit_group;")
#define CP_WAIT(n)  asm volatile("cp.async.wait_group %0;" :: "n"(n))

// ---------------- fused GEMM + dual-role epilogue (unchanged mainloop) ----------------
__global__ __launch_bounds__(256, 2) void k_gemm() {
    int t = blockIdx.x;
    int bm = 0;
    while (t >= NBLK - bm) { t -= NBLK - bm; bm++; }
    const int bn = bm + t;

    __shared__ __align__(16) __nv_bfloat16 sA[2][BM * LDA];
    __shared__ __align__(16) __nv_bfloat16 sB[2][BN * LDA];
    __shared__ float red_d[BM];
    __shared__ float red_p[BM];
    __shared__ float cred_d[BN];
    __shared__ float cred_p[BN];
    __shared__ float sWr[BM];

    const int tid  = threadIdx.x;
    const int warp = tid >> 5;
    const int lane = tid & 31;
    const int wm = warp >> 2;
    const int wn = warp & 3;
    const int rowBase = bm * BM;
    const int colBase = bn * BN;
    const bool doTrans = (bn > bm) && (bn < NFB);

    if (tid < BM) {
        red_d[tid] = 0.0f; red_p[tid] = 0.0f;
        cred_d[tid] = 0.0f; cred_p[tid] = 0.0f;
        sWr[tid] = g_w[rowBase + tid];
    }

    float acc[4][4][4];
#pragma unroll
    for (int a = 0; a < 4; a++)
#pragma unroll
        for (int b = 0; b < 4; b++)
#pragma unroll
            for (int c = 0; c < 4; c++) acc[a][b][c] = 0.0f;

    const int r0 = tid >> 2;
    const int r1 = r0 + 64;
    const int q  = tid & 3;
    const uint4* gA0 = reinterpret_cast<const uint4*>(g_Gb) + (size_t)(rowBase + r0) * (DIM / 8) + q;
    const uint4* gA1 = reinterpret_cast<const uint4*>(g_Gb) + (size_t)(rowBase + r1) * (DIM / 8) + q;
    const uint4* gB0 = reinterpret_cast<const uint4*>(g_Gb) + (size_t)(colBase + r0) * (DIM / 8) + q;
    const uint4* gB1 = reinterpret_cast<const uint4*>(g_Gb) + (size_t)(colBase + r1) * (DIM / 8) + q;

    uint32_t dA0[2], dA1[2], dB0[2], dB1[2];
#pragma unroll
    for (int s = 0; s < 2; s++) {
        dA0[s] = (uint32_t)__cvta_generic_to_shared(&sA[s][r0 * LDA + q * 8]);
        dA1[s] = (uint32_t)__cvta_generic_to_shared(&sA[s][r1 * LDA + q * 8]);
        dB0[s] = (uint32_t)__cvta_generic_to_shared(&sB[s][r0 * LDA + q * 8]);
        dB1[s] = (uint32_t)__cvta_generic_to_shared(&sB[s][r1 * LDA + q * 8]);
    }

    cp16(dA0[0], gA0); cp16(dA1[0], gA1);
    cp16(dB0[0], gB0); cp16(dB1[0], gB1);
    CP_COMMIT();

    const int KT = DIM / BK;
    const int aRow = wm * 64 + (lane & 15);
    const int aCol = (lane >> 4) << 3;
    const int bRow = wn * 32 + (lane & 7);
    const int bCol = ((lane >> 3) & 1) << 3;

    for (int kt = 0; kt < KT; kt++) {
        const int cur = kt & 1;
        if (kt + 1 < KT) {
            const int nxt = cur ^ 1;
            const int kq = (kt + 1) * 4;
            cp16(dA0[nxt], gA0 + kq); cp16(dA1[nxt], gA1 + kq);
            cp16(dB0[nxt], gB0 + kq); cp16(dB1[nxt], gB1 + kq);
            CP_COMMIT();
            CP_WAIT(1);
        } else {
            CP_WAIT(0);
        }
        __syncthreads();

        const uint32_t baseA = (uint32_t)__cvta_generic_to_shared(&sA[cur][0]);
        const uint32_t baseB = (uint32_t)__cvta_generic_to_shared(&sB[cur][0]);

#pragma unroll
        for (int kk = 0; kk < 2; kk++) {
            uint32_t af[4][4];
#pragma unroll
            for (int mt = 0; mt < 4; mt++) {
                uint32_t addr = baseA + (uint32_t)(((aRow + mt * 16) * LDA + kk * 16 + aCol) << 1);
                ldmatrix_x4(af[mt][0], af[mt][1], af[mt][2], af[mt][3], addr);
            }
            uint32_t bf[4][2];
#pragma unroll
            for (int nt = 0; nt < 4; nt++) {
                uint32_t addr = baseB + (uint32_t)(((bRow + nt * 8) * LDA + kk * 16 + bCol) << 1);
                ldmatrix_x2(bf[nt][0], bf[nt][1], addr);
            }
#pragma unroll
            for (int mt = 0; mt < 4; mt++)
#pragma unroll
                for (int nt = 0; nt < 4; nt++)
                    mma16816(acc[mt][nt], af[mt][0], af[mt][1], af[mt][2], af[mt][3],
                             bf[nt][0], bf[nt][1]);
        }
        if (kt + 1 < KT) __syncthreads();
    }

    // ---------- epilogue ----------
    const int g = lane >> 2;
    const int tl = lane & 3;

    float wv[4][2];
    int   cl[4][2];
    int   kc[4][2];
#pragma unroll
    for (int nt = 0; nt < 4; nt++)
#pragma unroll
        for (int j = 0; j < 2; j++) {
            int k = colBase + wn * 32 + nt * 8 + tl * 2 + j;
            kc[nt][j] = k;
            wv[nt][j] = g_w[k];
            cl[nt][j] = g_cls[k];
        }

    float cds[4][2], cps[4][2];
#pragma unroll
    for (int nt = 0; nt < 4; nt++)
#pragma unroll
        for (int j = 0; j < 2; j++) { cds[nt][j] = 0.0f; cps[nt][j] = 0.0f; }

#pragma unroll
    for (int mt = 0; mt < 4; mt++) {
#pragma unroll
        for (int h = 0; h < 2; h++) {
            const int lr = wm * 64 + mt * 16 + g + h * 8;
            const int i  = rowBase + lr;
            const int ti = g_cls[i];
            const float wr = sWr[lr];
            float ds = 0.0f, ps = 0.0f;
#pragma unroll
            for (int nt = 0; nt < 4; nt++)
#pragma unroll
                for (int j = 0; j < 2; j++) {
                    const float s = acc[mt][nt][h * 2 + j] * TAU_INV;
                    const float e = __expf(s);
                    ds += e * wv[nt][j];
                    float lg = 0.0f;
                    if (cl[nt][j] == ti && kc[nt][j] != i) lg = s;
                    ps += lg;
                    if (doTrans) {
                        cds[nt][j] += e * wr;
                        cps[nt][j] += lg;
                    }
                }
            ds += __shfl_xor_sync(0xffffffffu, ds, 1);
            ds += __shfl_xor_sync(0xffffffffu, ds, 2);
            ps += __shfl_xor_sync(0xffffffffu, ps, 1);
            ps += __shfl_xor_sync(0xffffffffu, ps, 2);
            if (tl == 0) {
                atomicAdd(&red_d[lr], ds);
                atomicAdd(&red_p[lr], ps);
            }
        }
    }

    if (doTrans) {
#pragma unroll
        for (int nt = 0; nt < 4; nt++)
#pragma unroll
            for (int j = 0; j < 2; j++) {
                float v = cds[nt][j], p = cps[nt][j];
                v += __shfl_xor_sync(0xffffffffu, v, 4);
                v += __shfl_xor_sync(0xffffffffu, v, 8);
                v += __shfl_xor_sync(0xffffffffu, v, 16);
                p += __shfl_xor_sync(0xffffffffu, p, 4);
                p += __shfl_xor_sync(0xffffffffu, p, 8);
                p += __shfl_xor_sync(0xffffffffu, p, 16);
                if (g == 0) {
                    const int ck = wn * 32 + nt * 8 + tl * 2 + j;
                    atomicAdd(&cred_d[ck], v);
                    atomicAdd(&cred_p[ck], p);
                }
            }
    }
    __syncthreads();

    if (tid < BM) {
        g_dp[bn * BATCH + rowBase + tid] = make_float2(red_d[tid], red_p[tid]);
        if (doTrans)
            g_dp[bm * BATCH + colBase + tid] = make_float2(cred_d[tid], cred_p[tid]);
    }
}

// ---------------- finalize: 256 blocks x 128 threads, 8 lanes per row ----------------
__global__ __launch_bounds__(128) void k_final(const int* __restrict__ targets,
                                               float* __restrict__ out) {
    const int tid = threadIdx.x;
    const int rloc = tid >> 3;               // 0..15 rows per block
    const int s    = tid & 7;                // 8 lanes per row
    const int r    = blockIdx.x * 16 + rloc;

    // 5 partials per lane: b = s, s+8, s+16, s+24, s+32 (MLP 5)
    float2 v0 = g_dp[(s +  0) * BATCH + r];
    float2 v1 = g_dp[(s +  8) * BATCH + r];
    float2 v2 = g_dp[(s + 16) * BATCH + r];
    float2 v3 = g_dp[(s + 24) * BATCH + r];
    float2 v4 = g_dp[(s + 32) * BATCH + r];
    float d = ((v0.x + v1.x) + (v2.x + v3.x)) + v4.x;
    float p = ((v0.y + v1.y) + (v2.y + v3.y)) + v4.y;

    // reduce across the 8 aligned lanes of this row
    d += __shfl_xor_sync(0xffffffffu, d, 1);
    d += __shfl_xor_sync(0xffffffffu, d, 2);
    d += __shfl_xor_sync(0xffffffffu, d, 4);
    p += __shfl_xor_sync(0xffffffffu, p, 1);
    p += __shfl_xor_sync(0xffffffffu, p, 2);
    p += __shfl_xor_sync(0xffffffffu, p, 4);

    if (s == 0) {
        const float np = (float)g_counts[targets[r]];
        g_rowv[r] = logf(d + EPSF) - p / np;
    }

    // last-block-done global reduction (deterministic fixed order)
    __threadfence();
    __shared__ int isLast;
    __shared__ float sred[128];
    if (tid == 0)
        isLast = (atomicAdd(&g_done, 1) == gridDim.x - 1) ? 1 : 0;
    __syncthreads();
    if (isLast) {
        float a0 = 0.f, a1 = 0.f, a2 = 0.f, a3 = 0.f;
#pragma unroll
        for (int i = 0; i < BATCH; i += 512) {
            a0 += g_rowv[i + tid];
            a1 += g_rowv[i + 128 + tid];
            a2 += g_rowv[i + 256 + tid];
            a3 += g_rowv[i + 384 + tid];
        }
        sred[tid] = (a0 + a1) + (a2 + a3);
        __syncthreads();
        for (int m = 64; m > 0; m >>= 1) {
            if (tid < m) sred[tid] += sred[tid + m];
            __syncthreads();
        }
        if (tid == 0) {
            out[0] = sred[0] / (float)BATCH;
            g_done = 0;    // reset for next graph replay
        }
    }
}

// ---------------- launch ----------------
extern "C" void kernel_launch(void* const* d_in, const int* in_sizes, int n_in,
                              void* d_out, int out_size) {
    const float* centers  = nullptr;
    const float* features = nullptr;
    const int*   targets  = nullptr;
    for (int i = 0; i < n_in; i++) {
        if (in_sizes[i] == BATCH)            targets  = (const int*)d_in[i];
        else if (in_sizes[i] == BATCH * DIM) features = (const float*)d_in[i];
        else if (in_sizes[i] == NC * DIM)    centers  = (const float*)d_in[i];
    }

    k_prep<<<1, 1024>>>(targets);
    k_convert<<<(NPAD * DIM / 16 + 255) / 256, 256>>>(features, centers);

    k_gemm<<<NTILE, 256>>>();

    k_final<<<BATCH / 16, 128>>>(targets, (float*)d_out);
}

// round 14
// speedup vs baseline: 1.0577x; 1.0111x over previous
#include <cuda_runtime.h>
#include <cuda_bf16.h>
#include <cstdint>

#define BATCH 4096
#define DIM   1024
#define NC    1000
#define NTOT  5096
#define NPAD  5120
#define TAU_INV 10.0f
#define EPSF 1e-8f

#define BM 128
#define BN 128
#define BK 32
#define LDA 40              // halves per smem row (32 data + 8 pad)
#define NBLK (NPAD / BN)    // 40
#define NFB  (BATCH / BM)   // 32
#define NTILE 784           // upper-triangle tiles: sum_{bm<32} (40-bm)

// ---- scratch ----
__device__ __nv_bfloat16 g_Gb[NPAD * DIM];
__device__ int   g_counts[NC];          // zero-init at load; re-zeroed by k_final last block
__device__ float2 g_dp[NBLK * BATCH];   // (denom, poslog) partials interleaved
__device__ float g_rowv[BATCH];
__device__ int   g_done = 0;            // ticket counter; last block resets to 0

// ---------------- convert (fp32->bf16, 16 elems/thread) + spread histogram ----------------
__global__ __launch_bounds__(256) void k_convert(const float* __restrict__ features,
                                                 const float* __restrict__ centers,
                                                 const int* __restrict__ targets) {
    int idx = blockIdx.x * blockDim.x + threadIdx.x;   // 0 .. NPAD*DIM/16-1

    // histogram: first BATCH global threads contribute one atomic each
    // (order-independent int adds -> deterministic; g_counts zeroed by prior k_final)
    if (idx < BATCH) atomicAdd(&g_counts[targets[idx]], 1);

    if (idx >= NPAD * DIM / 16) return;
    int row  = idx >> 6;           // 64 chunks of 16 per row
    int col0 = (idx & 63) << 4;

    float4 v[4];
    if (row < BATCH) {
        const float4* p = reinterpret_cast<const float4*>(features + (size_t)row * DIM + col0);
#pragma unroll
        for (int t = 0; t < 4; t++) v[t] = p[t];
    } else if (row < NTOT) {
        const float4* p = reinterpret_cast<const float4*>(centers + (size_t)(row - BATCH) * DIM + col0);
#pragma unroll
        for (int t = 0; t < 4; t++) v[t] = p[t];
    } else {
#pragma unroll
        for (int t = 0; t < 4; t++) v[t] = make_float4(0.f, 0.f, 0.f, 0.f);
    }
    uint4 pk[2];
    uint32_t* pw = reinterpret_cast<uint32_t*>(pk);
#pragma unroll
    for (int t = 0; t < 4; t++) {
        __nv_bfloat162 lo = __nv_bfloat162(__float2bfloat16_rn(v[t].x), __float2bfloat16_rn(v[t].y));
        __nv_bfloat162 hi = __nv_bfloat162(__float2bfloat16_rn(v[t].z), __float2bfloat16_rn(v[t].w));
        pw[t * 2 + 0] = *reinterpret_cast<uint32_t*>(&lo);
        pw[t * 2 + 1] = *reinterpret_cast<uint32_t*>(&hi);
    }
    uint4* dst = reinterpret_cast<uint4*>(g_Gb + (size_t)row * DIM + col0);
    dst[0] = pk[0];
    dst[1] = pk[1];
}

// ---------------- helpers ----------------
__device__ __forceinline__ void ldmatrix_x4(uint32_t& r0, uint32_t& r1, uint32_t& r2, uint32_t& r3,
                                            uint32_t addr) {
    asm volatile("ldmatrix.sync.aligned.m8n8.x4.shared.b16 {%0,%1,%2,%3}, [%4];"
                 : "=r"(r0), "=r"(r1), "=r"(r2), "=r"(r3) : "r"(addr));
}
__device__ __forceinline__ void ldmatrix_x2(uint32_t& r0, uint32_t& r1, uint32_t addr) {
    asm volatile("ldmatrix.sync.aligned.m8n8.x2.shared.b16 {%0,%1}, [%2];"
                 : "=r"(r0), "=r"(r1) : "r"(addr));
}
__device__ __forceinline__ void mma16816(float* c, uint32_t a0, uint32_t a1, uint32_t a2, uint32_t a3,
                                         uint32_t b0, uint32_t b1) {
    asm volatile(
        "mma.sync.aligned.m16n8k16.row.col.f32.bf16.bf16.f32 "
        "{%0,%1,%2,%3}, {%4,%5,%6,%7}, {%8,%9}, {%0,%1,%2,%3};"
        : "+f"(c[0]), "+f"(c[1]), "+f"(c[2]), "+f"(c[3])
        : "r"(a0), "r"(a1), "r"(a2), "r"(a3), "r"(b0), "r"(b1));
}
__device__ __forceinline__ void cp16(uint32_t dst, const void* src) {
    asm volatile("cp.async.cg.shared.global [%0], [%1], 16;" :: "r"(dst), "l"(src));
}
#define CP_COMMIT() asm volatile("cp.async.commit_group;")
#define CP_WAIT(n)  asm volatile("cp.async.wait_group %0;" :: "n"(n))

// weight/class for global column index k (bit-identical to the old g_w/g_cls tables)
__device__ __forceinline__ void wcls(int k, const int* __restrict__ targets, float& w, int& cl) {
    if (k < BATCH)      { cl = targets[k];  w = 1.0f / (float)(g_counts[cl] + 1); }
    else if (k < NTOT)  { cl = k - BATCH;   w = 1.0f / (float)(g_counts[cl] + 1); }
    else                { cl = -1;          w = 0.0f; }
}

// ---------------- fused GEMM + dual-role epilogue (mainloop unchanged) ----------------
__global__ __launch_bounds__(256, 2) void k_gemm(const int* __restrict__ targets) {
    int t = blockIdx.x;
    int bm = 0;
    while (t >= NBLK - bm) { t -= NBLK - bm; bm++; }
    const int bn = bm + t;

    __shared__ __align__(16) __nv_bfloat16 sA[2][BM * LDA];
    __shared__ __align__(16) __nv_bfloat16 sB[2][BN * LDA];
    __shared__ float red_d[BM];
    __shared__ float red_p[BM];
    __shared__ float cred_d[BN];
    __shared__ float cred_p[BN];
    __shared__ float sWr[BM];

    const int tid  = threadIdx.x;
    const int warp = tid >> 5;
    const int lane = tid & 31;
    const int wm = warp >> 2;
    const int wn = warp & 3;
    const int rowBase = bm * BM;
    const int colBase = bn * BN;
    const bool doTrans = (bn > bm) && (bn < NFB);

    if (tid < BM) {
        red_d[tid] = 0.0f; red_p[tid] = 0.0f;
        cred_d[tid] = 0.0f; cred_p[tid] = 0.0f;
        // rows are always < BATCH
        sWr[tid] = 1.0f / (float)(g_counts[targets[rowBase + tid]] + 1);
    }

    float acc[4][4][4];
#pragma unroll
    for (int a = 0; a < 4; a++)
#pragma unroll
        for (int b = 0; b < 4; b++)
#pragma unroll
            for (int c = 0; c < 4; c++) acc[a][b][c] = 0.0f;

    const int r0 = tid >> 2;
    const int r1 = r0 + 64;
    const int q  = tid & 3;
    const uint4* gA0 = reinterpret_cast<const uint4*>(g_Gb) + (size_t)(rowBase + r0) * (DIM / 8) + q;
    const uint4* gA1 = reinterpret_cast<const uint4*>(g_Gb) + (size_t)(rowBase + r1) * (DIM / 8) + q;
    const uint4* gB0 = reinterpret_cast<const uint4*>(g_Gb) + (size_t)(colBase + r0) * (DIM / 8) + q;
    const uint4* gB1 = reinterpret_cast<const uint4*>(g_Gb) + (size_t)(colBase + r1) * (DIM / 8) + q;

    uint32_t dA0[2], dA1[2], dB0[2], dB1[2];
#pragma unroll
    for (int s = 0; s < 2; s++) {
        dA0[s] = (uint32_t)__cvta_generic_to_shared(&sA[s][r0 * LDA + q * 8]);
        dA1[s] = (uint32_t)__cvta_generic_to_shared(&sA[s][r1 * LDA + q * 8]);
        dB0[s] = (uint32_t)__cvta_generic_to_shared(&sB[s][r0 * LDA + q * 8]);
        dB1[s] = (uint32_t)__cvta_generic_to_shared(&sB[s][r1 * LDA + q * 8]);
    }

    cp16(dA0[0], gA0); cp16(dA1[0], gA1);
    cp16(dB0[0], gB0); cp16(dB1[0], gB1);
    CP_COMMIT();

    const int KT = DIM / BK;
    const int aRow = wm * 64 + (lane & 15);
    const int aCol = (lane >> 4) << 3;
    const int bRow = wn * 32 + (lane & 7);
    const int bCol = ((lane >> 3) & 1) << 3;

    for (int kt = 0; kt < KT; kt++) {
        const int cur = kt & 1;
        if (kt + 1 < KT) {
            const int nxt = cur ^ 1;
            const int kq = (kt + 1) * 4;
            cp16(dA0[nxt], gA0 + kq); cp16(dA1[nxt], gA1 + kq);
            cp16(dB0[nxt], gB0 + kq); cp16(dB1[nxt], gB1 + kq);
            CP_COMMIT();
            CP_WAIT(1);
        } else {
            CP_WAIT(0);
        }
        __syncthreads();

        const uint32_t baseA = (uint32_t)__cvta_generic_to_shared(&sA[cur][0]);
        const uint32_t baseB = (uint32_t)__cvta_generic_to_shared(&sB[cur][0]);

#pragma unroll
        for (int kk = 0; kk < 2; kk++) {
            uint32_t af[4][4];
#pragma unroll
            for (int mt = 0; mt < 4; mt++) {
                uint32_t addr = baseA + (uint32_t)(((aRow + mt * 16) * LDA + kk * 16 + aCol) << 1);
                ldmatrix_x4(af[mt][0], af[mt][1], af[mt][2], af[mt][3], addr);
            }
            uint32_t bf[4][2];
#pragma unroll
            for (int nt = 0; nt < 4; nt++) {
                uint32_t addr = baseB + (uint32_t)(((bRow + nt * 8) * LDA + kk * 16 + bCol) << 1);
                ldmatrix_x2(bf[nt][0], bf[nt][1], addr);
            }
#pragma unroll
            for (int mt = 0; mt < 4; mt++)
#pragma unroll
                for (int nt = 0; nt < 4; nt++)
                    mma16816(acc[mt][nt], af[mt][0], af[mt][1], af[mt][2], af[mt][3],
                             bf[nt][0], bf[nt][1]);
        }
        if (kt + 1 < KT) __syncthreads();
    }

    // ---------- epilogue ----------
    const int g = lane >> 2;
    const int tl = lane & 3;

    float wv[4][2];
    int   cl[4][2];
    int   kc[4][2];
#pragma unroll
    for (int nt = 0; nt < 4; nt++)
#pragma unroll
        for (int j = 0; j < 2; j++) {
            int k = colBase + wn * 32 + nt * 8 + tl * 2 + j;
            kc[nt][j] = k;
            wcls(k, targets, wv[nt][j], cl[nt][j]);
        }

    float cds[4][2], cps[4][2];
#pragma unroll
    for (int nt = 0; nt < 4; nt++)
#pragma unroll
        for (int j = 0; j < 2; j++) { cds[nt][j] = 0.0f; cps[nt][j] = 0.0f; }

#pragma unroll
    for (int mt = 0; mt < 4; mt++) {
#pragma unroll
        for (int h = 0; h < 2; h++) {
            const int lr = wm * 64 + mt * 16 + g + h * 8;
            const int i  = rowBase + lr;
            const int ti = targets[i];        // rows always < BATCH
            const float wr = sWr[lr];
            float ds = 0.0f, ps = 0.0f;
#pragma unroll
            for (int nt = 0; nt < 4; nt++)
#pragma unroll
                for (int j = 0; j < 2; j++) {
                    const float s = acc[mt][nt][h * 2 + j] * TAU_INV;
                    const float e = __expf(s);
                    ds += e * wv[nt][j];
                    float lg = 0.0f;
                    if (cl[nt][j] == ti && kc[nt][j] != i) lg = s;
                    ps += lg;
                    if (doTrans) {
                        cds[nt][j] += e * wr;
                        cps[nt][j] += lg;
                    }
                }
            ds += __shfl_xor_sync(0xffffffffu, ds, 1);
            ds += __shfl_xor_sync(0xffffffffu, ds, 2);
            ps += __shfl_xor_sync(0xffffffffu, ps, 1);
            ps += __shfl_xor_sync(0xffffffffu, ps, 2);
            if (tl == 0) {
                atomicAdd(&red_d[lr], ds);
                atomicAdd(&red_p[lr], ps);
            }
        }
    }

    if (doTrans) {
#pragma unroll
        for (int nt = 0; nt < 4; nt++)
#pragma unroll
            for (int j = 0; j < 2; j++) {
                float v = cds[nt][j], p = cps[nt][j];
                v += __shfl_xor_sync(0xffffffffu, v, 4);
                v += __shfl_xor_sync(0xffffffffu, v, 8);
                v += __shfl_xor_sync(0xffffffffu, v, 16);
                p += __shfl_xor_sync(0xffffffffu, p, 4);
                p += __shfl_xor_sync(0xffffffffu, p, 8);
                p += __shfl_xor_sync(0xffffffffu, p, 16);
                if (g == 0) {
                    const int ck = wn * 32 + nt * 8 + tl * 2 + j;
                    atomicAdd(&cred_d[ck], v);
                    atomicAdd(&cred_p[ck], p);
                }
            }
    }
    __syncthreads();

    if (tid < BM) {
        g_dp[bn * BATCH + rowBase + tid] = make_float2(red_d[tid], red_p[tid]);
        if (doTrans)
            g_dp[bm * BATCH + colBase + tid] = make_float2(cred_d[tid], cred_p[tid]);
    }
}

// ---------------- finalize: 256 blocks x 128 threads; last block also resets state ----------------
__global__ __launch_bounds__(128) void k_final(const int* __restrict__ targets,
                                               float* __restrict__ out) {
    const int tid = threadIdx.x;
    const int rloc = tid >> 3;               // 0..15 rows per block
    const int s    = tid & 7;                // 8 lanes per row
    const int r    = blockIdx.x * 16 + rloc;

    // 5 partials per lane: b = s, s+8, s+16, s+24, s+32 (MLP 5)
    float2 v0 = g_dp[(s +  0) * BATCH + r];
    float2 v1 = g_dp[(s +  8) * BATCH + r];
    float2 v2 = g_dp[(s + 16) * BATCH + r];
    float2 v3 = g_dp[(s + 24) * BATCH + r];
    float2 v4 = g_dp[(s + 32) * BATCH + r];
    float d = ((v0.x + v1.x) + (v2.x + v3.x)) + v4.x;
    float p = ((v0.y + v1.y) + (v2.y + v3.y)) + v4.y;

    // reduce across the 8 aligned lanes of this row
    d += __shfl_xor_sync(0xffffffffu, d, 1);
    d += __shfl_xor_sync(0xffffffffu, d, 2);
    d += __shfl_xor_sync(0xffffffffu, d, 4);
    p += __shfl_xor_sync(0xffffffffu, p, 1);
    p += __shfl_xor_sync(0xffffffffu, p, 2);
    p += __shfl_xor_sync(0xffffffffu, p, 4);

    if (s == 0) {
        const float np = (float)g_counts[targets[r]];
        g_rowv[r] = logf(d + EPSF) - p / np;
    }

    // last-block-done global reduction (deterministic fixed order)
    __threadfence();
    __shared__ int isLast;
    __shared__ float sred[128];
    if (tid == 0)
        isLast = (atomicAdd(&g_done, 1) == gridDim.x - 1) ? 1 : 0;
    __syncthreads();
    if (isLast) {
        float a0 = 0.f, a1 = 0.f, a2 = 0.f, a3 = 0.f;
#pragma unroll
        for (int i = 0; i < BATCH; i += 512) {
            a0 += g_rowv[i + tid];
            a1 += g_rowv[i + 128 + tid];
            a2 += g_rowv[i + 256 + tid];
            a3 += g_rowv[i + 384 + tid];
        }
        sred[tid] = (a0 + a1) + (a2 + a3);
        __syncthreads();
        for (int m = 64; m > 0; m >>= 1) {
            if (tid < m) sred[tid] += sred[tid + m];
            __syncthreads();
        }
        // reset state for next graph replay (all blocks have finished reading
        // g_counts before the last ticket arrives)
        for (int c = tid; c < NC; c += 128) g_counts[c] = 0;
        if (tid == 0) {
            out[0] = sred[0] / (float)BATCH;
            g_done = 0;
        }
    }
}

// ---------------- launch ----------------
extern "C" void kernel_launch(void* const* d_in, const int* in_sizes, int n_in,
                              void* d_out, int out_size) {
    const float* centers  = nullptr;
    const float* features = nullptr;
    const int*   targets  = nullptr;
    for (int i = 0; i < n_in; i++) {
        if (in_sizes[i] == BATCH)            targets  = (const int*)d_in[i];
        else if (in_sizes[i] == BATCH * DIM) features = (const float*)d_in[i];
        else if (in_sizes[i] == NC * DIM)    centers  = (const float*)d_in[i];
    }

    k_convert<<<(NPAD * DIM / 16 + 255) / 256, 256>>>(features, centers, targets);

    k_gemm<<<NTILE, 256>>>(targets);

    k_final<<<BATCH / 16, 128>>>(targets, (float*)d_out);
}